// round 2
// baseline (speedup 1.0000x reference)
#include <cuda_runtime.h>
#include <math.h>

#define B_DIM 4
#define N_DIM 10
#define C_DIM 256
#define L_Q 1024
#define L_S 1024
#define K_SHOT 5
#define G_DIM 2  // N_DIM / K_SHOT

#define Q_ELEMS (B_DIM * C_DIM * L_Q)         // 1,048,576
#define S_ELEMS (N_DIM * C_DIM * L_S)         // 2,621,440
#define QOUT_ELEMS (B_DIM * G_DIM * C_DIM * L_Q)  // 2,097,152

// SMEM layout (floats), stride 65 for bank-conflict freedom
#define QS_STR 65
#define SMEM_FLOATS (C_DIM * QS_STR /*Qs*/ + C_DIM * QS_STR /*Scm*/ + 64 * QS_STR /*Pt*/ + 192)
#define SMEM_BYTES (SMEM_FLOATS * 4)

__device__ float g_means[2];
__device__ float g_part[2][512];

// ---------------- deterministic mean reductions ----------------
__global__ void partial_sum_kernel(const float* __restrict__ x, int n, int slot) {
    __shared__ float sm[256];
    float local = 0.f;
    for (int i = blockIdx.x * 256 + threadIdx.x; i < n; i += 512 * 256)
        local += x[i];
    sm[threadIdx.x] = local;
    __syncthreads();
    for (int off = 128; off > 0; off >>= 1) {
        if (threadIdx.x < off) sm[threadIdx.x] += sm[threadIdx.x + off];
        __syncthreads();
    }
    if (threadIdx.x == 0) g_part[slot][blockIdx.x] = sm[0];
}

__global__ void final_mean_kernel() {
    __shared__ float sm[512];
    int t = threadIdx.x;
    sm[t] = g_part[0][t];
    __syncthreads();
    for (int off = 256; off > 0; off >>= 1) {
        if (t < off) sm[t] += sm[t + off];
        __syncthreads();
    }
    if (t == 0) g_means[0] = sm[0] / (float)Q_ELEMS;
    __syncthreads();
    sm[t] = g_part[1][t];
    __syncthreads();
    for (int off = 256; off > 0; off >>= 1) {
        if (t < off) sm[t] += sm[t + off];
        __syncthreads();
    }
    if (t == 0) g_means[1] = sm[0] / (float)S_ELEMS;
}

// ---------------- q_out: centered query, replicated over G ----------------
__global__ void qout_kernel(const float* __restrict__ q, float* __restrict__ out) {
    int idx = blockIdx.x * 256 + threadIdx.x;
    if (idx >= QOUT_ELEMS) return;
    int l = idx & (L_Q - 1);
    int c = (idx >> 10) & (C_DIM - 1);
    int b = idx >> 19;  // idx = ((b*2 + g)*256 + c)*1024 + l
    out[idx] = q[((b * C_DIM + c) << 10) + l] - g_means[0];
}

// ---------------- fused attention + K-shot average ----------------
// grid: 128 CTAs = g(2) * b(4) * l-tile(16); block: 256 threads
__global__ __launch_bounds__(256, 1)
void attn_kernel(const float* __restrict__ qf, const float* __restrict__ sf,
                 float* __restrict__ out_aligned) {
    extern __shared__ float sm[];
    float* Qs  = sm;                       // [256][65]  Q tile, K(c)-major
    float* Scm = Qs + C_DIM * QS_STR;      // [256][65]  S tile, K(c)-major
    float* Pt  = Scm + C_DIM * QS_STR;     // [64][65]   sim/P transposed: [s][l]
    float* rowM = Pt + 64 * QS_STR;        // [64]
    float* rowL = rowM + 64;               // [64]
    float* rowScale = rowL + 64;           // [64]

    const int tid = threadIdx.x;
    const int bid = blockIdx.x;
    const int lt = bid & 15;
    const int b  = (bid >> 4) & 3;
    const int g  = bid >> 6;
    const int l0 = lt << 6;

    const float mq = g_means[0];
    const float ms = g_means[1];

    // Load centered Q tile once: Qs[c][l] = q[b][c][l0+l] - mq
    const float* qb = qf + (size_t)b * C_DIM * L_Q;
    for (int idx = tid; idx < C_DIM * 64; idx += 256) {
        int c = idx >> 6, l = idx & 63;
        Qs[c * QS_STR + l] = qb[c * L_Q + l0 + l] - mq;
    }

    // GEMM1 thread mapping: 16x16, each thread 4x4 (rows ty1*4+i, cols tx1*4+j)
    const int ty1 = tid >> 4, tx1 = tid & 15;
    // GEMM2 / output mapping: warp wy -> rows wy*8+i; lane -> cols lane+32*j
    const int wy = tid >> 5, lane = tid & 31;

    float avg[64];
#pragma unroll
    for (int i = 0; i < 64; i++) avg[i] = 0.f;

    for (int k = 0; k < K_SHOT; k++) {
        const float* sb = sf + (size_t)(g * K_SHOT + k) * C_DIM * L_S;
        float acc[64];
#pragma unroll
        for (int i = 0; i < 64; i++) acc[i] = 0.f;
        __syncthreads();  // previous k's consumers done before stats reset
        if (tid < 64) { rowM[tid] = -INFINITY; rowL[tid] = 0.f; }

        for (int t = 0; t < 16; t++) {
            __syncthreads();  // Scm/Pt free, stats visible
            const int s0 = t << 6;
            for (int idx = tid; idx < C_DIM * 64; idx += 256) {
                int c = idx >> 6, s = idx & 63;
                Scm[c * QS_STR + s] = sb[c * L_S + s0 + s] - ms;
            }
            __syncthreads();

            // ---- GEMM1: sim[64l x 64s] over c ----
            float simr[16];
#pragma unroll
            for (int i = 0; i < 16; i++) simr[i] = 0.f;
#pragma unroll 4
            for (int c = 0; c < C_DIM; c++) {
                const float* qr = Qs + c * QS_STR + (ty1 << 2);
                const float* sr = Scm + c * QS_STR + (tx1 << 2);
                float a0 = qr[0], a1 = qr[1], a2 = qr[2], a3 = qr[3];
                float b0 = sr[0], b1 = sr[1], b2 = sr[2], b3 = sr[3];
                simr[0]  += a0 * b0; simr[1]  += a0 * b1; simr[2]  += a0 * b2; simr[3]  += a0 * b3;
                simr[4]  += a1 * b0; simr[5]  += a1 * b1; simr[6]  += a1 * b2; simr[7]  += a1 * b3;
                simr[8]  += a2 * b0; simr[9]  += a2 * b1; simr[10] += a2 * b2; simr[11] += a2 * b3;
                simr[12] += a3 * b0; simr[13] += a3 * b1; simr[14] += a3 * b2; simr[15] += a3 * b3;
            }
#pragma unroll
            for (int i = 0; i < 4; i++)
#pragma unroll
                for (int j = 0; j < 4; j++)
                    Pt[(tx1 * 4 + j) * QS_STR + (ty1 * 4 + i)] = simr[i * 4 + j];
            __syncthreads();

            // ---- online softmax: warp wy owns rows wy*8..wy*8+7 ----
#pragma unroll
            for (int r = 0; r < 8; r++) {
                const int l = wy * 8 + r;
                float v0 = Pt[lane * QS_STR + l];
                float v1 = Pt[(lane + 32) * QS_STR + l];
                float tmax = fmaxf(v0, v1);
#pragma unroll
                for (int off = 16; off > 0; off >>= 1)
                    tmax = fmaxf(tmax, __shfl_xor_sync(0xffffffffu, tmax, off));
                const float mold = rowM[l];
                const float mnew = fmaxf(mold, tmax);
                const float p0 = __expf(v0 - mnew);
                const float p1 = __expf(v1 - mnew);
                Pt[lane * QS_STR + l] = p0;
                Pt[(lane + 32) * QS_STR + l] = p1;
                float tsum = p0 + p1;
#pragma unroll
                for (int off = 16; off > 0; off >>= 1)
                    tsum += __shfl_xor_sync(0xffffffffu, tsum, off);
                if (lane == 0) {
                    const float scl = __expf(mold - mnew);
                    rowScale[l] = scl;
                    rowL[l] = rowL[l] * scl + tsum;
                    rowM[l] = mnew;
                }
            }
            __syncthreads();

            // ---- rescale + GEMM2: acc[8l x 8c] += P[l][s] * S[c][s] ----
            float scl8[8];
#pragma unroll
            for (int i = 0; i < 8; i++) scl8[i] = rowScale[wy * 8 + i];
#pragma unroll
            for (int i = 0; i < 8; i++)
#pragma unroll
                for (int j = 0; j < 8; j++)
                    acc[i * 8 + j] *= scl8[i];

#pragma unroll 2
            for (int s = 0; s < 64; s++) {
                float pv[8], sv[8];
#pragma unroll
                for (int i = 0; i < 8; i++) pv[i] = Pt[s * QS_STR + wy * 8 + i];
#pragma unroll
                for (int j = 0; j < 8; j++) sv[j] = Scm[(lane + 32 * j) * QS_STR + s];
#pragma unroll
                for (int i = 0; i < 8; i++)
#pragma unroll
                    for (int j = 0; j < 8; j++)
                        acc[i * 8 + j] += pv[i] * sv[j];
            }
        }  // s tiles

        // finalize this shot: avg += acc / rowsum  (rowL visible via pre-GEMM2 sync)
        float inv[8];
#pragma unroll
        for (int i = 0; i < 8; i++) inv[i] = 1.0f / rowL[wy * 8 + i];
#pragma unroll
        for (int i = 0; i < 8; i++)
#pragma unroll
            for (int j = 0; j < 8; j++)
                avg[i * 8 + j] += acc[i * 8 + j] * inv[i];
    }  // k shots

    // write aligned: out[((g*4 + b)*256 + c)*1024 + l]
    const float invK = 1.0f / (float)K_SHOT;
#pragma unroll
    for (int i = 0; i < 8; i++) {
        const int l = l0 + wy * 8 + i;
#pragma unroll
        for (int j = 0; j < 8; j++) {
            const int c = lane + 32 * j;
            out_aligned[(((g * B_DIM + b) * C_DIM + c) << 10) + l] = avg[i * 8 + j] * invK;
        }
    }
}

extern "C" void kernel_launch(void* const* d_in, const int* in_sizes, int n_in,
                              void* d_out, int out_size) {
    const float* q = (const float*)d_in[0];
    const float* s = (const float*)d_in[1];
    float* out = (float*)d_out;
    float* out_aligned = out + (size_t)QOUT_ELEMS;

    cudaFuncSetAttribute(attn_kernel, cudaFuncAttributeMaxDynamicSharedMemorySize, SMEM_BYTES);

    partial_sum_kernel<<<512, 256>>>(q, Q_ELEMS, 0);
    partial_sum_kernel<<<512, 256>>>(s, S_ELEMS, 1);
    final_mean_kernel<<<1, 512>>>();
    qout_kernel<<<(QOUT_ELEMS + 255) / 256, 256>>>(q, out);
    attn_kernel<<<G_DIM * B_DIM * 16, 256, SMEM_BYTES>>>(q, s, out_aligned);
}

// round 5
// speedup vs baseline: 1.7756x; 1.7756x over previous
#include <cuda_runtime.h>
#include <cuda_bf16.h>
#include <math.h>
#include <stdint.h>

#define B_DIM 4
#define N_DIM 10
#define C_DIM 256
#define L_Q 1024
#define L_S 1024
#define K_SHOT 5
#define G_DIM 2
#define SHIFT_CONST 40.0f

#define Q_ELEMS (B_DIM * C_DIM * L_Q)
#define S_ELEMS (N_DIM * C_DIM * L_S)
#define QOUT_ELEMS (B_DIM * G_DIM * C_DIM * L_Q)

__device__ float g_means[2];
__device__ float g_part[2][512];

// centered bf16 hi/lo splits (static __device__ scratch — no runtime alloc)
__device__ __nv_bfloat16 g_qthi[B_DIM * L_Q * C_DIM];   // Q^T [b][l][c]
__device__ __nv_bfloat16 g_qtlo[B_DIM * L_Q * C_DIM];
__device__ __nv_bfloat16 g_sthi[N_DIM * L_S * C_DIM];   // S^T [n][s][c]
__device__ __nv_bfloat16 g_stlo[N_DIM * L_S * C_DIM];
__device__ __nv_bfloat16 g_shi[N_DIM * C_DIM * L_S];    // S   [n][c][s]
__device__ __nv_bfloat16 g_slo[N_DIM * C_DIM * L_S];

// ---------------- deterministic mean reductions ----------------
__global__ void partial_sum_kernel(const float* __restrict__ x, int n, int slot) {
    __shared__ float sm[256];
    float local = 0.f;
    for (int i = blockIdx.x * 256 + threadIdx.x; i < n; i += 512 * 256)
        local += x[i];
    sm[threadIdx.x] = local;
    __syncthreads();
    for (int off = 128; off > 0; off >>= 1) {
        if (threadIdx.x < off) sm[threadIdx.x] += sm[threadIdx.x + off];
        __syncthreads();
    }
    if (threadIdx.x == 0) g_part[slot][blockIdx.x] = sm[0];
}

__global__ void final_mean_kernel() {
    __shared__ float sm[512];
    int t = threadIdx.x;
    sm[t] = g_part[0][t];
    __syncthreads();
    for (int off = 256; off > 0; off >>= 1) {
        if (t < off) sm[t] += sm[t + off];
        __syncthreads();
    }
    if (t == 0) g_means[0] = sm[0] / (float)Q_ELEMS;
    __syncthreads();
    sm[t] = g_part[1][t];
    __syncthreads();
    for (int off = 256; off > 0; off >>= 1) {
        if (t < off) sm[t] += sm[t + off];
        __syncthreads();
    }
    if (t == 0) g_means[1] = sm[0] / (float)S_ELEMS;
}

// ---------------- q_out ----------------
__global__ void qout_kernel(const float* __restrict__ q, float* __restrict__ out) {
    int idx = blockIdx.x * 256 + threadIdx.x;
    if (idx >= QOUT_ELEMS) return;
    int l = idx & (L_Q - 1);
    int c = (idx >> 10) & (C_DIM - 1);
    int b = idx >> 19;
    out[idx] = q[((b * C_DIM + c) << 10) + l] - g_means[0];
}

// ---------------- prep: centered bf16 hi/lo splits ----------------
__device__ __forceinline__ void split_write(__nv_bfloat16* hi, __nv_bfloat16* lo,
                                            size_t idx, float v) {
    __nv_bfloat16 h = __float2bfloat16(v);
    hi[idx] = h;
    lo[idx] = __float2bfloat16(v - __bfloat162float(h));
}

__global__ void prep_qt_kernel(const float* __restrict__ q) {
    __shared__ float t[32][33];
    int b = blockIdx.z, c0 = blockIdx.y * 32, l0 = blockIdx.x * 32;
    int x = threadIdx.x, y = threadIdx.y;  // 32 x 8
    for (int i = 0; i < 32; i += 8)
        t[y + i][x] = q[(((size_t)b * C_DIM + c0 + y + i) << 10) + l0 + x];
    __syncthreads();
    float mq = g_means[0];
    for (int i = 0; i < 32; i += 8) {
        float v = t[x][y + i] - mq;
        size_t oi = ((size_t)b * L_Q + (l0 + y + i)) * C_DIM + c0 + x;
        split_write(g_qthi, g_qtlo, oi, v);
    }
}

__global__ void prep_st_kernel(const float* __restrict__ s) {
    __shared__ float t[32][33];
    int n = blockIdx.z, c0 = blockIdx.y * 32, l0 = blockIdx.x * 32;
    int x = threadIdx.x, y = threadIdx.y;
    for (int i = 0; i < 32; i += 8)
        t[y + i][x] = s[(((size_t)n * C_DIM + c0 + y + i) << 10) + l0 + x];
    __syncthreads();
    float ms = g_means[1];
    for (int i = 0; i < 32; i += 8) {
        float v = t[x][y + i] - ms;
        size_t oi = ((size_t)n * L_S + (l0 + y + i)) * C_DIM + c0 + x;
        split_write(g_sthi, g_stlo, oi, v);
    }
}

__global__ void prep_s_kernel(const float* __restrict__ s) {
    int i = blockIdx.x * 256 + threadIdx.x;
    if (i >= S_ELEMS) return;
    float v = s[i] - g_means[1];
    split_write(g_shi, g_slo, (size_t)i, v);
}

// ---------------- mma / cp.async helpers ----------------
__device__ __forceinline__ uint32_t smem_u32(const void* p) {
    uint32_t a;
    asm("{ .reg .u64 t; cvta.to.shared.u64 t, %1; cvt.u32.u64 %0, t; }" : "=r"(a) : "l"(p));
    return a;
}
__device__ __forceinline__ void mma16816(float* c, const uint32_t* a, const uint32_t* b) {
    asm volatile(
        "mma.sync.aligned.m16n8k16.row.col.f32.bf16.bf16.f32 "
        "{%0,%1,%2,%3}, {%4,%5,%6,%7}, {%8,%9}, {%0,%1,%2,%3};"
        : "+f"(c[0]), "+f"(c[1]), "+f"(c[2]), "+f"(c[3])
        : "r"(a[0]), "r"(a[1]), "r"(a[2]), "r"(a[3]), "r"(b[0]), "r"(b[1]));
}
__device__ __forceinline__ void cpa16(uint32_t saddr, const void* g) {
    asm volatile("cp.async.cg.shared.global [%0], [%1], 16;" :: "r"(saddr), "l"(g) : "memory");
}
#define CP_COMMIT() asm volatile("cp.async.commit_group;" ::: "memory")
#define CP_WAIT0()  asm volatile("cp.async.wait_group 0;" ::: "memory")

// SMEM strides (bf16 elems) — padded so row-stride mod 32 banks == 4 (conflict-free)
#define QSTR 264
#define STSTR 72
#define PSTR 136
#define SCSTR 136
// byte offsets
#define O_QHI 0
#define O_QLO (O_QHI + 64 * QSTR * 2)       // 33792
#define O_STHI (O_QLO + 64 * QSTR * 2)      // 67584
#define O_STLO (O_STHI + 128 * STSTR * 2)   // 86016
#define O_PHI (O_STLO + 128 * STSTR * 2)    // 104448
#define O_PLO (O_PHI + 64 * PSTR * 2)       // 121856
#define O_SCHI (O_PLO + 64 * PSTR * 2)      // 139264
#define O_SCLO (O_SCHI + 64 * SCSTR * 2)    // 156672
#define O_LP  (O_SCLO + 64 * SCSTR * 2)     // 174080
#define SMEM_TOTAL (O_LP + 64 * 4 * 4)      // 175104

// ---------------- fused HMMA attention ----------------
// grid 128 = g(2) * b(4) * ltile(16); block 256 (8 warps, 2x4)
__global__ __launch_bounds__(256, 1)
void attn_mma_kernel(float* __restrict__ out_aligned) {
    extern __shared__ char sm[];
    const int tid = threadIdx.x;
    const int w = tid >> 5, lane = tid & 31;
    const int r = lane >> 2, q = lane & 3;
    const int wr = w >> 2, wc = w & 3;

    const int bid = blockIdx.x;
    const int lt = bid & 15, b = (bid >> 4) & 3, g = bid >> 6;
    const int l0 = lt << 6;

    float* Lp = (float*)(sm + O_LP);  // [64][4]

    // resident Q tile: rows 64 (l), cols 256 (c), hi+lo
    {
        const __nv_bfloat16* qh = g_qthi + ((size_t)b * L_Q + l0) * C_DIM;
        const __nv_bfloat16* ql = g_qtlo + ((size_t)b * L_Q + l0) * C_DIM;
        for (int i = tid; i < 64 * 32; i += 256) {
            int row = i >> 5, c16 = i & 31;
            uint32_t so = row * QSTR * 2 + c16 * 16;
            const size_t go = (size_t)row * C_DIM + c16 * 8;
            cpa16(smem_u32(sm + O_QHI) + so, qh + go);
            cpa16(smem_u32(sm + O_QLO) + so, ql + go);
        }
        CP_COMMIT();
    }

    float* outp = out_aligned + ((size_t)((g * B_DIM + b) * C_DIM) << 10);

    for (int k = 0; k < K_SHOT; k++) {
        const int n = g * K_SHOT + k;
        const __nv_bfloat16* sth = g_sthi + (size_t)n * L_S * C_DIM;
        const __nv_bfloat16* stl = g_stlo + (size_t)n * L_S * C_DIM;
        const __nv_bfloat16* sh  = g_shi + (size_t)n * C_DIM * L_S;
        const __nv_bfloat16* sl  = g_slo + (size_t)n * C_DIM * L_S;

        Lp[tid] = 0.f;  // 256 = 64*4 entries exactly

        float acc2[4][2][2][4];
#pragma unroll
        for (int a = 0; a < 4; a++)
#pragma unroll
            for (int m = 0; m < 2; m++)
#pragma unroll
                for (int j = 0; j < 2; j++)
#pragma unroll
                    for (int v = 0; v < 4; v++) acc2[a][m][j][v] = 0.f;

        for (int st = 0; st < 8; st++) {
            const int s0 = st << 7;

            // ======== GEMM1: sim[64 x 128] over c ========
            float acc1[2][4][4];
#pragma unroll
            for (int m = 0; m < 2; m++)
#pragma unroll
                for (int j = 0; j < 4; j++)
#pragma unroll
                    for (int v = 0; v < 4; v++) acc1[m][j][v] = 0.f;

            for (int cc = 0; cc < 4; cc++) {
                __syncthreads();
                // stage S^T chunk: rows s0..s0+127, cols cc*64..+63 (hi/lo)
                for (int i = tid; i < 128 * 8; i += 256) {
                    int srow = i >> 3, c16 = i & 7;
                    uint32_t so = srow * STSTR * 2 + c16 * 16;
                    const size_t go = (size_t)(s0 + srow) * C_DIM + cc * 64 + c16 * 8;
                    cpa16(smem_u32(sm + O_STHI) + so, sth + go);
                    cpa16(smem_u32(sm + O_STLO) + so, stl + go);
                }
                CP_COMMIT();
                CP_WAIT0();
                __syncthreads();

#pragma unroll
                for (int ks = 0; ks < 4; ks++) {
                    uint32_t ah[2][4], al[2][4];
#pragma unroll
                    for (int m = 0; m < 2; m++) {
                        int row0 = wr * 32 + m * 16 + r;
                        int col = cc * 64 + ks * 16 + q * 2;
                        const char* ph = sm + O_QHI;
                        const char* pl = sm + O_QLO;
                        ah[m][0] = *(const uint32_t*)(ph + row0 * QSTR * 2 + col * 2);
                        ah[m][1] = *(const uint32_t*)(ph + (row0 + 8) * QSTR * 2 + col * 2);
                        ah[m][2] = *(const uint32_t*)(ph + row0 * QSTR * 2 + (col + 8) * 2);
                        ah[m][3] = *(const uint32_t*)(ph + (row0 + 8) * QSTR * 2 + (col + 8) * 2);
                        al[m][0] = *(const uint32_t*)(pl + row0 * QSTR * 2 + col * 2);
                        al[m][1] = *(const uint32_t*)(pl + (row0 + 8) * QSTR * 2 + col * 2);
                        al[m][2] = *(const uint32_t*)(pl + row0 * QSTR * 2 + (col + 8) * 2);
                        al[m][3] = *(const uint32_t*)(pl + (row0 + 8) * QSTR * 2 + (col + 8) * 2);
                    }
                    uint32_t bh[4][2], bl[4][2];
#pragma unroll
                    for (int j = 0; j < 4; j++) {
                        int srow = wc * 32 + j * 8 + r;
                        int col = ks * 16 + q * 2;
                        const char* ph = sm + O_STHI;
                        const char* pl = sm + O_STLO;
                        bh[j][0] = *(const uint32_t*)(ph + srow * STSTR * 2 + col * 2);
                        bh[j][1] = *(const uint32_t*)(ph + srow * STSTR * 2 + (col + 8) * 2);
                        bl[j][0] = *(const uint32_t*)(pl + srow * STSTR * 2 + col * 2);
                        bl[j][1] = *(const uint32_t*)(pl + srow * STSTR * 2 + (col + 8) * 2);
                    }
#pragma unroll
                    for (int m = 0; m < 2; m++)
#pragma unroll
                        for (int j = 0; j < 4; j++) {
                            mma16816(acc1[m][j], ah[m], bh[j]);
                            mma16816(acc1[m][j], ah[m], bl[j]);
                            mma16816(acc1[m][j], al[m], bh[j]);
                        }
                }
            }

            // ======== softmax: P = exp(sim - SHIFT), hi/lo -> SMEM ========
            {
                float rowsum[2][2] = {{0.f, 0.f}, {0.f, 0.f}};
                float pv[2][4][4];
#pragma unroll
                for (int m = 0; m < 2; m++)
#pragma unroll
                    for (int j = 0; j < 4; j++) {
#pragma unroll
                        for (int v = 0; v < 4; v++)
                            pv[m][j][v] = __expf(acc1[m][j][v] - SHIFT_CONST);
                        rowsum[m][0] += pv[m][j][0] + pv[m][j][1];
                        rowsum[m][1] += pv[m][j][2] + pv[m][j][3];
                    }
#pragma unroll
                for (int m = 0; m < 2; m++)
#pragma unroll
                    for (int h = 0; h < 2; h++) {
                        rowsum[m][h] += __shfl_xor_sync(0xffffffffu, rowsum[m][h], 1);
                        rowsum[m][h] += __shfl_xor_sync(0xffffffffu, rowsum[m][h], 2);
                    }
#pragma unroll
                for (int m = 0; m < 2; m++)
#pragma unroll
                    for (int j = 0; j < 4; j++)
#pragma unroll
                        for (int h = 0; h < 2; h++) {
                            int prow = wr * 32 + m * 16 + r + h * 8;
                            int pcol = wc * 32 + j * 8 + q * 2;
                            float p0 = pv[m][j][h * 2 + 0];
                            float p1 = pv[m][j][h * 2 + 1];
                            __nv_bfloat162 th = __floats2bfloat162_rn(p0, p1);
                            float r0 = p0 - __low2float(th);
                            float r1 = p1 - __high2float(th);
                            __nv_bfloat162 tl = __floats2bfloat162_rn(r0, r1);
                            *(uint32_t*)(sm + O_PHI + prow * PSTR * 2 + pcol * 2) =
                                *reinterpret_cast<uint32_t*>(&th);
                            *(uint32_t*)(sm + O_PLO + prow * PSTR * 2 + pcol * 2) =
                                *reinterpret_cast<uint32_t*>(&tl);
                        }
                if (q == 0) {
#pragma unroll
                    for (int m = 0; m < 2; m++)
#pragma unroll
                        for (int h = 0; h < 2; h++) {
                            int prow = wr * 32 + m * 16 + r + h * 8;
                            Lp[prow * 4 + wc] += rowsum[m][h];
                        }
                }
            }
            __syncthreads();

            // ======== GEMM2: aligned[64 x 256] += P * S^T ========
            for (int nc = 0; nc < 4; nc++) {
                __syncthreads();
                // stage S chunk: rows c = nc*64..+63, cols s0..s0+127 (hi/lo)
                for (int i = tid; i < 64 * 16; i += 256) {
                    int crow = i >> 4, c16 = i & 15;
                    uint32_t so = crow * SCSTR * 2 + c16 * 16;
                    const size_t go = (size_t)(nc * 64 + crow) * L_S + s0 + c16 * 8;
                    cpa16(smem_u32(sm + O_SCHI) + so, sh + go);
                    cpa16(smem_u32(sm + O_SCLO) + so, sl + go);
                }
                CP_COMMIT();
                CP_WAIT0();
                __syncthreads();

#pragma unroll
                for (int ks = 0; ks < 8; ks++) {
                    uint32_t ah[2][4], al[2][4];
#pragma unroll
                    for (int m = 0; m < 2; m++) {
                        int row0 = wr * 32 + m * 16 + r;
                        int col = ks * 16 + q * 2;
                        const char* ph = sm + O_PHI;
                        const char* pl = sm + O_PLO;
                        ah[m][0] = *(const uint32_t*)(ph + row0 * PSTR * 2 + col * 2);
                        ah[m][1] = *(const uint32_t*)(ph + (row0 + 8) * PSTR * 2 + col * 2);
                        ah[m][2] = *(const uint32_t*)(ph + row0 * PSTR * 2 + (col + 8) * 2);
                        ah[m][3] = *(const uint32_t*)(ph + (row0 + 8) * PSTR * 2 + (col + 8) * 2);
                        al[m][0] = *(const uint32_t*)(pl + row0 * PSTR * 2 + col * 2);
                        al[m][1] = *(const uint32_t*)(pl + (row0 + 8) * PSTR * 2 + col * 2);
                        al[m][2] = *(const uint32_t*)(pl + row0 * PSTR * 2 + (col + 8) * 2);
                        al[m][3] = *(const uint32_t*)(pl + (row0 + 8) * PSTR * 2 + (col + 8) * 2);
                    }
                    uint32_t bh[2][2], bl[2][2];
#pragma unroll
                    for (int j = 0; j < 2; j++) {
                        int crow = wc * 16 + j * 8 + r;
                        int col = ks * 16 + q * 2;
                        const char* ph = sm + O_SCHI;
                        const char* pl = sm + O_SCLO;
                        bh[j][0] = *(const uint32_t*)(ph + crow * SCSTR * 2 + col * 2);
                        bh[j][1] = *(const uint32_t*)(ph + crow * SCSTR * 2 + (col + 8) * 2);
                        bl[j][0] = *(const uint32_t*)(pl + crow * SCSTR * 2 + col * 2);
                        bl[j][1] = *(const uint32_t*)(pl + crow * SCSTR * 2 + (col + 8) * 2);
                    }
#pragma unroll
                    for (int m = 0; m < 2; m++)
#pragma unroll
                        for (int j = 0; j < 2; j++) {
                            mma16816(acc2[nc][m][j], ah[m], bh[j]);
                            mma16816(acc2[nc][m][j], ah[m], bl[j]);
                            mma16816(acc2[nc][m][j], al[m], bh[j]);
                        }
                }
            }
        }  // s-tiles

        // ======== shot epilogue: out += acc2 * (0.2 / L[row]) ========
        {
            float scl[2][2];
#pragma unroll
            for (int m = 0; m < 2; m++)
#pragma unroll
                for (int h = 0; h < 2; h++) {
                    int row = wr * 32 + m * 16 + r + h * 8;
                    float L = Lp[row * 4] + Lp[row * 4 + 1] + Lp[row * 4 + 2] + Lp[row * 4 + 3];
                    scl[m][h] = 0.2f / L;
                }
#pragma unroll
            for (int nc = 0; nc < 4; nc++)
#pragma unroll
                for (int m = 0; m < 2; m++)
#pragma unroll
                    for (int j = 0; j < 2; j++)
#pragma unroll
                        for (int v = 0; v < 4; v++) {
                            int h = v >> 1;
                            int row = wr * 32 + m * 16 + r + h * 8;
                            int col = nc * 64 + wc * 16 + j * 8 + q * 2 + (v & 1);
                            size_t oi = ((size_t)col << 10) + l0 + row;
                            float val = acc2[nc][m][j][v] * scl[m][h];
                            if (k == 0) outp[oi] = val;
                            else        outp[oi] += val;
                        }
        }
        __syncthreads();  // epilogue Lp reads done before next shot's reset
    }  // shots
}

extern "C" void kernel_launch(void* const* d_in, const int* in_sizes, int n_in,
                              void* d_out, int out_size) {
    const float* q = (const float*)d_in[0];
    const float* s = (const float*)d_in[1];
    float* out = (float*)d_out;
    float* out_aligned = out + (size_t)QOUT_ELEMS;

    cudaFuncSetAttribute(attn_mma_kernel, cudaFuncAttributeMaxDynamicSharedMemorySize, SMEM_TOTAL);

    partial_sum_kernel<<<512, 256>>>(q, Q_ELEMS, 0);
    partial_sum_kernel<<<512, 256>>>(s, S_ELEMS, 1);
    final_mean_kernel<<<1, 512>>>();

    dim3 tb(32, 8);
    prep_qt_kernel<<<dim3(L_Q / 32, C_DIM / 32, B_DIM), tb>>>(q);
    prep_st_kernel<<<dim3(L_S / 32, C_DIM / 32, N_DIM), tb>>>(s);
    prep_s_kernel<<<(S_ELEMS + 255) / 256, 256>>>(s);

    qout_kernel<<<(QOUT_ELEMS + 255) / 256, 256>>>(q, out);
    attn_mma_kernel<<<G_DIM * B_DIM * 16, 256, SMEM_TOTAL>>>(out_aligned);
}

// round 6
// speedup vs baseline: 3.4526x; 1.9445x over previous
#include <cuda_runtime.h>
#include <cuda_bf16.h>
#include <math.h>
#include <stdint.h>

#define B_DIM 4
#define N_DIM 10
#define C_DIM 256
#define L_Q 1024
#define L_S 1024
#define K_SHOT 5
#define G_DIM 2
#define SHIFT_CONST 40.0f

#define Q_ELEMS (B_DIM * C_DIM * L_Q)
#define S_ELEMS (N_DIM * C_DIM * L_S)
#define QOUT_ELEMS (B_DIM * G_DIM * C_DIM * L_Q)

__device__ float g_means[2];
__device__ float g_part[2][512];

// centered bf16 hi/lo splits (static __device__ scratch)
__device__ __nv_bfloat16 g_qthi[B_DIM * L_Q * C_DIM];   // Q^T [b][l][c]
__device__ __nv_bfloat16 g_qtlo[B_DIM * L_Q * C_DIM];
__device__ __nv_bfloat16 g_sthi[N_DIM * L_S * C_DIM];   // S^T [n][s][c]
__device__ __nv_bfloat16 g_stlo[N_DIM * L_S * C_DIM];
__device__ __nv_bfloat16 g_shi[N_DIM * C_DIM * L_S];    // S   [n][c][s]
__device__ __nv_bfloat16 g_slo[N_DIM * C_DIM * L_S];

// ---------------- deterministic mean reductions ----------------
__global__ void partial_sum_kernel(const float* __restrict__ x, int n, int slot) {
    __shared__ float sm[256];
    float local = 0.f;
    for (int i = blockIdx.x * 256 + threadIdx.x; i < n; i += 512 * 256)
        local += x[i];
    sm[threadIdx.x] = local;
    __syncthreads();
    for (int off = 128; off > 0; off >>= 1) {
        if (threadIdx.x < off) sm[threadIdx.x] += sm[threadIdx.x + off];
        __syncthreads();
    }
    if (threadIdx.x == 0) g_part[slot][blockIdx.x] = sm[0];
}

__global__ void final_mean_kernel() {
    __shared__ float sm[512];
    int t = threadIdx.x;
    sm[t] = g_part[0][t];
    __syncthreads();
    for (int off = 256; off > 0; off >>= 1) {
        if (t < off) sm[t] += sm[t + off];
        __syncthreads();
    }
    if (t == 0) g_means[0] = sm[0] / (float)Q_ELEMS;
    __syncthreads();
    sm[t] = g_part[1][t];
    __syncthreads();
    for (int off = 256; off > 0; off >>= 1) {
        if (t < off) sm[t] += sm[t + off];
        __syncthreads();
    }
    if (t == 0) g_means[1] = sm[0] / (float)S_ELEMS;
}

// ---------------- q_out ----------------
__global__ void qout_kernel(const float* __restrict__ q, float* __restrict__ out) {
    int idx = blockIdx.x * 256 + threadIdx.x;
    if (idx >= QOUT_ELEMS) return;
    int l = idx & (L_Q - 1);
    int c = (idx >> 10) & (C_DIM - 1);
    int b = idx >> 19;
    out[idx] = q[((b * C_DIM + c) << 10) + l] - g_means[0];
}

// ---------------- prep: centered bf16 hi/lo splits ----------------
__device__ __forceinline__ void split_write(__nv_bfloat16* hi, __nv_bfloat16* lo,
                                            size_t idx, float v) {
    __nv_bfloat16 h = __float2bfloat16(v);
    hi[idx] = h;
    lo[idx] = __float2bfloat16(v - __bfloat162float(h));
}

__global__ void prep_qt_kernel(const float* __restrict__ q) {
    __shared__ float t[32][33];
    int b = blockIdx.z, c0 = blockIdx.y * 32, l0 = blockIdx.x * 32;
    int x = threadIdx.x, y = threadIdx.y;  // 32 x 8
    for (int i = 0; i < 32; i += 8)
        t[y + i][x] = q[(((size_t)b * C_DIM + c0 + y + i) << 10) + l0 + x];
    __syncthreads();
    float mq = g_means[0];
    for (int i = 0; i < 32; i += 8) {
        float v = t[x][y + i] - mq;
        size_t oi = ((size_t)b * L_Q + (l0 + y + i)) * C_DIM + c0 + x;
        split_write(g_qthi, g_qtlo, oi, v);
    }
}

__global__ void prep_st_kernel(const float* __restrict__ s) {
    __shared__ float t[32][33];
    int n = blockIdx.z, c0 = blockIdx.y * 32, l0 = blockIdx.x * 32;
    int x = threadIdx.x, y = threadIdx.y;
    for (int i = 0; i < 32; i += 8)
        t[y + i][x] = s[(((size_t)n * C_DIM + c0 + y + i) << 10) + l0 + x];
    __syncthreads();
    float ms = g_means[1];
    for (int i = 0; i < 32; i += 8) {
        float v = t[x][y + i] - ms;
        size_t oi = ((size_t)n * L_S + (l0 + y + i)) * C_DIM + c0 + x;
        split_write(g_sthi, g_stlo, oi, v);
    }
}

__global__ void prep_s_kernel(const float* __restrict__ s) {
    int i = blockIdx.x * 256 + threadIdx.x;
    if (i >= S_ELEMS) return;
    float v = s[i] - g_means[1];
    split_write(g_shi, g_slo, (size_t)i, v);
}

// ---------------- mma / cp.async / ldmatrix helpers ----------------
__device__ __forceinline__ uint32_t smem_u32(const void* p) {
    uint32_t a;
    asm("{ .reg .u64 t; cvta.to.shared.u64 t, %1; cvt.u32.u64 %0, t; }" : "=r"(a) : "l"(p));
    return a;
}
__device__ __forceinline__ void mma16816(float* c, const uint32_t* a, const uint32_t* b) {
    asm volatile(
        "mma.sync.aligned.m16n8k16.row.col.f32.bf16.bf16.f32 "
        "{%0,%1,%2,%3}, {%4,%5,%6,%7}, {%8,%9}, {%0,%1,%2,%3};"
        : "+f"(c[0]), "+f"(c[1]), "+f"(c[2]), "+f"(c[3])
        : "r"(a[0]), "r"(a[1]), "r"(a[2]), "r"(a[3]), "r"(b[0]), "r"(b[1]));
}
__device__ __forceinline__ void ldsm4(uint32_t* r, uint32_t addr) {
    asm volatile("ldmatrix.sync.aligned.m8n8.x4.shared.b16 {%0,%1,%2,%3}, [%4];"
                 : "=r"(r[0]), "=r"(r[1]), "=r"(r[2]), "=r"(r[3]) : "r"(addr));
}
__device__ __forceinline__ void cpa16(uint32_t saddr, const void* g) {
    asm volatile("cp.async.cg.shared.global [%0], [%1], 16;" :: "r"(saddr), "l"(g) : "memory");
}
#define CP_COMMIT() asm volatile("cp.async.commit_group;" ::: "memory")
#define CP_WAIT0()  asm volatile("cp.async.wait_group 0;" ::: "memory")
#define CP_WAIT1()  asm volatile("cp.async.wait_group 1;" ::: "memory")

// A-fragment ldmatrix address: 16x16 tile at (row0, col); strideB bytes/row
__device__ __forceinline__ uint32_t a_addr(uint32_t base, int row0, int col,
                                           int strideB, int lane) {
    int gsel = lane >> 3, ln = lane & 7;
    return base + (uint32_t)((row0 + ((gsel & 1) << 3) + ln) * strideB
                             + ((col + ((gsel >> 1) << 3)) << 1));
}
// B-fragment ldmatrix address: 16 n-rows x 16 k at (row0, col)
__device__ __forceinline__ uint32_t b_addr(uint32_t base, int row0, int col,
                                           int strideB, int lane) {
    int gsel = lane >> 3, ln = lane & 7;
    return base + (uint32_t)((row0 + ((gsel >> 1) << 3) + ln) * strideB
                             + ((col + ((gsel & 1) << 3)) << 1));
}

// SMEM layout (byte strides chosen so stride % 128 == 16 -> conflict-free LDSM)
#define QSTRB 528     // 264 bf16
#define STSTRB 144    // 72 bf16
#define PSTRB 272     // 136 bf16
#define SCSTRB 272
#define O_QHI 0
#define O_QLO 33792
#define O_PHI 67584
#define O_PLO 84992
#define O_STAGE 102400
#define BUFB 36864
#define LOOFF 18432          // hi->lo offset within one staging buffer
#define O_EPI (O_STAGE + BUFB)  // epilogue staging aliases buffer 1
#define EPSTR 65
#define O_LP 176128
#define SMEM_TOTAL (O_LP + 64 * 4 * 4)   // 177152

__device__ __forceinline__ void stage_st_chunk(uint32_t dhi,
        const __nv_bfloat16* sth, const __nv_bfloat16* stl,
        int s0, int cc, int tid) {
    for (int i = tid; i < 128 * 8; i += 256) {
        int r = i >> 3, c16 = i & 7;
        uint32_t so = (uint32_t)(r * STSTRB + c16 * 16);
        size_t go = (size_t)(s0 + r) * C_DIM + cc * 64 + c16 * 8;
        cpa16(dhi + so, sth + go);
        cpa16(dhi + LOOFF + so, stl + go);
    }
}
__device__ __forceinline__ void stage_sc_chunk(uint32_t dhi,
        const __nv_bfloat16* sh, const __nv_bfloat16* sl,
        int s0, int nc, int tid) {
    for (int i = tid; i < 64 * 16; i += 256) {
        int r = i >> 4, c16 = i & 15;
        uint32_t so = (uint32_t)(r * SCSTRB + c16 * 16);
        size_t go = (size_t)(nc * 64 + r) * L_S + s0 + c16 * 8;
        cpa16(dhi + so, sh + go);
        cpa16(dhi + LOOFF + so, sl + go);
    }
}

// ---------------- fused HMMA attention ----------------
// grid 128 = g(2) * b(4) * ltile(16); block 256 (8 warps, wr(2) x wc(4))
__global__ __launch_bounds__(256, 1)
void attn_mma_kernel(float* __restrict__ out_aligned) {
    extern __shared__ char sm[];
    const uint32_t smb = smem_u32(sm);
    const int tid = threadIdx.x;
    const int w = tid >> 5, lane = tid & 31;
    const int r = lane >> 2, q = lane & 3;
    const int wr = w >> 2, wc = w & 3;

    const int bid = blockIdx.x;
    const int lt = bid & 15, b = (bid >> 4) & 3, g = bid >> 6;
    const int l0 = lt << 6;

    float* Lp = (float*)(sm + O_LP);  // [64][4]
    float* epi = (float*)(sm + O_EPI);

    // prologue: resident Q tile (64 x 256, hi+lo) + first S^T chunk, one group
    {
        const __nv_bfloat16* qh = g_qthi + ((size_t)b * L_Q + l0) * C_DIM;
        const __nv_bfloat16* ql = g_qtlo + ((size_t)b * L_Q + l0) * C_DIM;
        for (int i = tid; i < 64 * 32; i += 256) {
            int row = i >> 5, c16 = i & 31;
            uint32_t so = (uint32_t)(row * QSTRB + c16 * 16);
            const size_t go = (size_t)row * C_DIM + c16 * 8;
            cpa16(smb + O_QHI + so, qh + go);
            cpa16(smb + O_QLO + so, ql + go);
        }
        const int n0 = g * K_SHOT;
        stage_st_chunk(smb + O_STAGE, g_sthi + (size_t)n0 * L_S * C_DIM,
                       g_stlo + (size_t)n0 * L_S * C_DIM, 0, 0, tid);
        CP_COMMIT();
    }

    float* outp = out_aligned + ((size_t)((g * B_DIM + b) * C_DIM) << 10);

    for (int k = 0; k < K_SHOT; k++) {
        const int n = g * K_SHOT + k;
        const __nv_bfloat16* sth = g_sthi + (size_t)n * L_S * C_DIM;
        const __nv_bfloat16* stl = g_stlo + (size_t)n * L_S * C_DIM;
        const __nv_bfloat16* sh  = g_shi + (size_t)n * C_DIM * L_S;
        const __nv_bfloat16* sl  = g_slo + (size_t)n * C_DIM * L_S;

        Lp[tid] = 0.f;

        float acc2[4][2][2][4];
#pragma unroll
        for (int a = 0; a < 4; a++)
#pragma unroll
            for (int m = 0; m < 2; m++)
#pragma unroll
                for (int j = 0; j < 2; j++)
#pragma unroll
                    for (int v = 0; v < 4; v++) acc2[a][m][j][v] = 0.f;

        for (int st = 0; st < 8; st++) {
            const int s0 = st << 7;

            // ======== GEMM1: sim[64 x 128] over c, double-buffered ========
            float acc1[2][4][4];
#pragma unroll
            for (int m = 0; m < 2; m++)
#pragma unroll
                for (int j = 0; j < 4; j++)
#pragma unroll
                    for (int v = 0; v < 4; v++) acc1[m][j][v] = 0.f;

            for (int cc = 0; cc < 4; cc++) {
                const uint32_t cur = smb + O_STAGE + (uint32_t)(cc & 1) * BUFB;
                if (cc < 3) {
                    stage_st_chunk(smb + O_STAGE + (uint32_t)((cc + 1) & 1) * BUFB,
                                   sth, stl, s0, cc + 1, tid);
                    CP_COMMIT();
                    CP_WAIT1();
                } else {
                    CP_WAIT0();
                }
                __syncthreads();

#pragma unroll
                for (int ks = 0; ks < 4; ks++) {
                    const int colq = cc * 64 + ks * 16;
                    uint32_t ah[2][4], al_[2][4];
                    ldsm4(ah[0],  a_addr(smb + O_QHI, wr * 32,      colq, QSTRB, lane));
                    ldsm4(ah[1],  a_addr(smb + O_QHI, wr * 32 + 16, colq, QSTRB, lane));
                    ldsm4(al_[0], a_addr(smb + O_QLO, wr * 32,      colq, QSTRB, lane));
                    ldsm4(al_[1], a_addr(smb + O_QLO, wr * 32 + 16, colq, QSTRB, lane));
                    uint32_t bh[4][2], bl[4][2];
                    {
                        uint32_t t[4];
                        ldsm4(t, b_addr(cur, wc * 32,      ks * 16, STSTRB, lane));
                        bh[0][0] = t[0]; bh[0][1] = t[1]; bh[1][0] = t[2]; bh[1][1] = t[3];
                        ldsm4(t, b_addr(cur, wc * 32 + 16, ks * 16, STSTRB, lane));
                        bh[2][0] = t[0]; bh[2][1] = t[1]; bh[3][0] = t[2]; bh[3][1] = t[3];
                        ldsm4(t, b_addr(cur + LOOFF, wc * 32,      ks * 16, STSTRB, lane));
                        bl[0][0] = t[0]; bl[0][1] = t[1]; bl[1][0] = t[2]; bl[1][1] = t[3];
                        ldsm4(t, b_addr(cur + LOOFF, wc * 32 + 16, ks * 16, STSTRB, lane));
                        bl[2][0] = t[0]; bl[2][1] = t[1]; bl[3][0] = t[2]; bl[3][1] = t[3];
                    }
#pragma unroll
                    for (int m = 0; m < 2; m++)
#pragma unroll
                        for (int j = 0; j < 4; j++) {
                            mma16816(acc1[m][j], ah[m], bh[j]);
                            mma16816(acc1[m][j], ah[m], bl[j]);
                            mma16816(acc1[m][j], al_[m], bh[j]);
                        }
                }
                __syncthreads();
            }

            // prefetch first GEMM2 chunk (buffer 0 is free: last read at cc=2)
            stage_sc_chunk(smb + O_STAGE, sh, sl, s0, 0, tid);
            CP_COMMIT();

            // ======== softmax: P = exp(sim - SHIFT), hi/lo -> SMEM ========
            {
                float rowsum[2][2] = {{0.f, 0.f}, {0.f, 0.f}};
                float pv[2][4][4];
#pragma unroll
                for (int m = 0; m < 2; m++)
#pragma unroll
                    for (int j = 0; j < 4; j++) {
#pragma unroll
                        for (int v = 0; v < 4; v++)
                            pv[m][j][v] = __expf(acc1[m][j][v] - SHIFT_CONST);
                        rowsum[m][0] += pv[m][j][0] + pv[m][j][1];
                        rowsum[m][1] += pv[m][j][2] + pv[m][j][3];
                    }
#pragma unroll
                for (int m = 0; m < 2; m++)
#pragma unroll
                    for (int h = 0; h < 2; h++) {
                        rowsum[m][h] += __shfl_xor_sync(0xffffffffu, rowsum[m][h], 1);
                        rowsum[m][h] += __shfl_xor_sync(0xffffffffu, rowsum[m][h], 2);
                    }
#pragma unroll
                for (int m = 0; m < 2; m++)
#pragma unroll
                    for (int j = 0; j < 4; j++)
#pragma unroll
                        for (int h = 0; h < 2; h++) {
                            int prow = wr * 32 + m * 16 + r + h * 8;
                            int pcol = wc * 32 + j * 8 + q * 2;
                            float p0 = pv[m][j][h * 2 + 0];
                            float p1 = pv[m][j][h * 2 + 1];
                            __nv_bfloat162 th = __floats2bfloat162_rn(p0, p1);
                            float r0 = p0 - __low2float(th);
                            float r1 = p1 - __high2float(th);
                            __nv_bfloat162 tl = __floats2bfloat162_rn(r0, r1);
                            *(uint32_t*)(sm + O_PHI + prow * PSTRB + pcol * 2) =
                                *reinterpret_cast<uint32_t*>(&th);
                            *(uint32_t*)(sm + O_PLO + prow * PSTRB + pcol * 2) =
                                *reinterpret_cast<uint32_t*>(&tl);
                        }
                if (q == 0) {
#pragma unroll
                    for (int m = 0; m < 2; m++)
#pragma unroll
                        for (int h = 0; h < 2; h++) {
                            int prow = wr * 32 + m * 16 + r + h * 8;
                            Lp[prow * 4 + wc] += rowsum[m][h];
                        }
                }
            }
            __syncthreads();  // P + Lp visible

            // ======== GEMM2: aligned[64 x 256] += P * S^T, double-buffered ========
            for (int nc = 0; nc < 4; nc++) {
                const uint32_t cur = smb + O_STAGE + (uint32_t)(nc & 1) * BUFB;
                if (nc < 3) {
                    stage_sc_chunk(smb + O_STAGE + (uint32_t)((nc + 1) & 1) * BUFB,
                                   sh, sl, s0, nc + 1, tid);
                    CP_COMMIT();
                    CP_WAIT1();
                } else {
                    CP_WAIT0();
                }
                __syncthreads();

#pragma unroll
                for (int ks = 0; ks < 8; ks++) {
                    uint32_t ah[2][4], al_[2][4];
                    ldsm4(ah[0],  a_addr(smb + O_PHI, wr * 32,      ks * 16, PSTRB, lane));
                    ldsm4(ah[1],  a_addr(smb + O_PHI, wr * 32 + 16, ks * 16, PSTRB, lane));
                    ldsm4(al_[0], a_addr(smb + O_PLO, wr * 32,      ks * 16, PSTRB, lane));
                    ldsm4(al_[1], a_addr(smb + O_PLO, wr * 32 + 16, ks * 16, PSTRB, lane));
                    uint32_t bh[2][2], bl[2][2];
                    {
                        uint32_t t[4];
                        ldsm4(t, b_addr(cur, wc * 16, ks * 16, SCSTRB, lane));
                        bh[0][0] = t[0]; bh[0][1] = t[1]; bh[1][0] = t[2]; bh[1][1] = t[3];
                        ldsm4(t, b_addr(cur + LOOFF, wc * 16, ks * 16, SCSTRB, lane));
                        bl[0][0] = t[0]; bl[0][1] = t[1]; bl[1][0] = t[2]; bl[1][1] = t[3];
                    }
#pragma unroll
                    for (int m = 0; m < 2; m++)
#pragma unroll
                        for (int j = 0; j < 2; j++) {
                            mma16816(acc2[nc][m][j], ah[m], bh[j]);
                            mma16816(acc2[nc][m][j], ah[m], bl[j]);
                            mma16816(acc2[nc][m][j], al_[m], bh[j]);
                        }
                }
                __syncthreads();
            }

            // prefetch next s-tile's (or next shot's) first S^T chunk into buffer 0
            {
                int k2 = k, st2 = st + 1;
                if (st2 == 8) { st2 = 0; k2 = k + 1; }
                if (k2 < K_SHOT) {
                    const int n2 = g * K_SHOT + k2;
                    stage_st_chunk(smb + O_STAGE,
                                   g_sthi + (size_t)n2 * L_S * C_DIM,
                                   g_stlo + (size_t)n2 * L_S * C_DIM,
                                   st2 << 7, 0, tid);
                    CP_COMMIT();
                }
            }
        }  // s-tiles

        // ======== shot epilogue: out += acc2 * (0.2/L[row]), coalesced ========
        {
            float scl[2][2];
#pragma unroll
            for (int m = 0; m < 2; m++)
#pragma unroll
                for (int h = 0; h < 2; h++) {
                    int row = wr * 32 + m * 16 + r + h * 8;
                    float L = Lp[row * 4] + Lp[row * 4 + 1] + Lp[row * 4 + 2] + Lp[row * 4 + 3];
                    scl[m][h] = 0.2f / L;
                }
            for (int nc = 0; nc < 4; nc++) {
                __syncthreads();  // epi region free
#pragma unroll
                for (int m = 0; m < 2; m++)
#pragma unroll
                    for (int j = 0; j < 2; j++)
#pragma unroll
                        for (int v = 0; v < 4; v++) {
                            int row = wr * 32 + m * 16 + r + (v >> 1) * 8;
                            int col = wc * 16 + j * 8 + q * 2 + (v & 1);
                            epi[row * EPSTR + col] = acc2[nc][m][j][v] * scl[m][v >> 1];
                        }
                __syncthreads();
#pragma unroll
                for (int cidx = 0; cidx < 8; cidx++) {
                    int colL = w * 8 + cidx;
                    size_t oa = ((size_t)(nc * 64 + colL) << 10) + l0 + lane * 2;
                    float v0 = epi[(lane * 2) * EPSTR + colL];
                    float v1 = epi[(lane * 2 + 1) * EPSTR + colL];
                    float2* gp = reinterpret_cast<float2*>(outp + oa);
                    if (k == 0) {
                        *gp = make_float2(v0, v1);
                    } else {
                        float2 o = *gp;
                        *gp = make_float2(o.x + v0, o.y + v1);
                    }
                }
            }
            __syncthreads();  // epilogue reads done before next shot reuses buffers
        }
    }  // shots
}

extern "C" void kernel_launch(void* const* d_in, const int* in_sizes, int n_in,
                              void* d_out, int out_size) {
    const float* q = (const float*)d_in[0];
    const float* s = (const float*)d_in[1];
    float* out = (float*)d_out;
    float* out_aligned = out + (size_t)QOUT_ELEMS;

    cudaFuncSetAttribute(attn_mma_kernel, cudaFuncAttributeMaxDynamicSharedMemorySize, SMEM_TOTAL);

    partial_sum_kernel<<<512, 256>>>(q, Q_ELEMS, 0);
    partial_sum_kernel<<<512, 256>>>(s, S_ELEMS, 1);
    final_mean_kernel<<<1, 512>>>();

    dim3 tb(32, 8);
    prep_qt_kernel<<<dim3(L_Q / 32, C_DIM / 32, B_DIM), tb>>>(q);
    prep_st_kernel<<<dim3(L_S / 32, C_DIM / 32, N_DIM), tb>>>(s);
    prep_s_kernel<<<(S_ELEMS + 255) / 256, 256>>>(s);

    qout_kernel<<<(QOUT_ELEMS + 255) / 256, 256>>>(q, out);
    attn_mma_kernel<<<G_DIM * B_DIM * 16, 256, SMEM_TOTAL>>>(out_aligned);
}

// round 9
// speedup vs baseline: 3.7763x; 1.0938x over previous
#include <cuda_runtime.h>
#include <cuda_bf16.h>
#include <math.h>
#include <stdint.h>

#define B_DIM 4
#define N_DIM 10
#define C_DIM 256
#define L_Q 1024
#define L_S 1024
#define K_SHOT 5
#define G_DIM 2
#define SHIFT_CONST 40.0f

#define Q_ELEMS (B_DIM * C_DIM * L_Q)
#define S_ELEMS (N_DIM * C_DIM * L_S)
#define QOUT_ELEMS (B_DIM * G_DIM * C_DIM * L_Q)

__device__ float g_means[2];
__device__ float g_part[2][512];

// centered bf16 hi/lo splits (static __device__ scratch)
__device__ __nv_bfloat16 g_qthi[B_DIM * L_Q * C_DIM];   // Q^T [b][l][c]
__device__ __nv_bfloat16 g_qtlo[B_DIM * L_Q * C_DIM];
__device__ __nv_bfloat16 g_sthi[N_DIM * L_S * C_DIM];   // S^T [n][s][c]
__device__ __nv_bfloat16 g_stlo[N_DIM * L_S * C_DIM];
__device__ __nv_bfloat16 g_shi[N_DIM * C_DIM * L_S];    // S   [n][c][s]
__device__ __nv_bfloat16 g_slo[N_DIM * C_DIM * L_S];

// ---------------- deterministic mean reductions ----------------
__global__ void partial_sum_kernel(const float* __restrict__ x, int n, int slot) {
    __shared__ float sm[256];
    float local = 0.f;
    for (int i = blockIdx.x * 256 + threadIdx.x; i < n; i += 512 * 256)
        local += x[i];
    sm[threadIdx.x] = local;
    __syncthreads();
    for (int off = 128; off > 0; off >>= 1) {
        if (threadIdx.x < off) sm[threadIdx.x] += sm[threadIdx.x + off];
        __syncthreads();
    }
    if (threadIdx.x == 0) g_part[slot][blockIdx.x] = sm[0];
}

__global__ void final_mean_kernel() {
    __shared__ float sm[512];
    int t = threadIdx.x;
    sm[t] = g_part[0][t];
    __syncthreads();
    for (int off = 256; off > 0; off >>= 1) {
        if (t < off) sm[t] += sm[t + off];
        __syncthreads();
    }
    if (t == 0) g_means[0] = sm[0] / (float)Q_ELEMS;
    __syncthreads();
    sm[t] = g_part[1][t];
    __syncthreads();
    for (int off = 256; off > 0; off >>= 1) {
        if (t < off) sm[t] += sm[t + off];
        __syncthreads();
    }
    if (t == 0) g_means[1] = sm[0] / (float)S_ELEMS;
}

// ---------------- q_out ----------------
__global__ void qout_kernel(const float* __restrict__ q, float* __restrict__ out) {
    int idx = blockIdx.x * 256 + threadIdx.x;
    if (idx >= QOUT_ELEMS) return;
    int l = idx & (L_Q - 1);
    int c = (idx >> 10) & (C_DIM - 1);
    int b = idx >> 19;
    out[idx] = q[((b * C_DIM + c) << 10) + l] - g_means[0];
}

// ---------------- prep: centered bf16 hi/lo splits ----------------
__device__ __forceinline__ void split_write(__nv_bfloat16* hi, __nv_bfloat16* lo,
                                            size_t idx, float v) {
    __nv_bfloat16 h = __float2bfloat16(v);
    hi[idx] = h;
    lo[idx] = __float2bfloat16(v - __bfloat162float(h));
}

__global__ void prep_qt_kernel(const float* __restrict__ q) {
    __shared__ float t[32][33];
    int b = blockIdx.z, c0 = blockIdx.y * 32, l0 = blockIdx.x * 32;
    int x = threadIdx.x, y = threadIdx.y;  // 32 x 8
    for (int i = 0; i < 32; i += 8)
        t[y + i][x] = q[(((size_t)b * C_DIM + c0 + y + i) << 10) + l0 + x];
    __syncthreads();
    float mq = g_means[0];
    for (int i = 0; i < 32; i += 8) {
        float v = t[x][y + i] - mq;
        size_t oi = ((size_t)b * L_Q + (l0 + y + i)) * C_DIM + c0 + x;
        split_write(g_qthi, g_qtlo, oi, v);
    }
}

// fused: S^T splits (transposed) + S splits (linear) in one pass over s
__global__ void prep_st_kernel(const float* __restrict__ s) {
    __shared__ float t[32][33];
    int n = blockIdx.z, c0 = blockIdx.y * 32, l0 = blockIdx.x * 32;
    int x = threadIdx.x, y = threadIdx.y;
    float ms = g_means[1];
    float lv[4];
#pragma unroll
    for (int i = 0; i < 4; i++) {
        lv[i] = s[(((size_t)n * C_DIM + c0 + y + i * 8) << 10) + l0 + x];
        t[y + i * 8][x] = lv[i];
    }
#pragma unroll
    for (int i = 0; i < 4; i++) {
        // linear split (same layout as input)
        size_t li = (((size_t)n * C_DIM + c0 + y + i * 8) << 10) + l0 + x;
        split_write(g_shi, g_slo, li, lv[i] - ms);
    }
    __syncthreads();
#pragma unroll
    for (int i = 0; i < 4; i++) {
        float v = t[x][y + i * 8] - ms;
        size_t oi = ((size_t)n * L_S + (l0 + y + i * 8)) * C_DIM + c0 + x;
        split_write(g_sthi, g_stlo, oi, v);
    }
}

// ---------------- mma / cp.async / ldmatrix helpers ----------------
__device__ __forceinline__ uint32_t smem_u32(const void* p) {
    uint32_t a;
    asm("{ .reg .u64 t; cvta.to.shared.u64 t, %1; cvt.u32.u64 %0, t; }" : "=r"(a) : "l"(p));
    return a;
}
__device__ __forceinline__ void mma16816(float* c, const uint32_t* a, const uint32_t* b) {
    asm volatile(
        "mma.sync.aligned.m16n8k16.row.col.f32.bf16.bf16.f32 "
        "{%0,%1,%2,%3}, {%4,%5,%6,%7}, {%8,%9}, {%0,%1,%2,%3};"
        : "+f"(c[0]), "+f"(c[1]), "+f"(c[2]), "+f"(c[3])
        : "r"(a[0]), "r"(a[1]), "r"(a[2]), "r"(a[3]), "r"(b[0]), "r"(b[1]));
}
__device__ __forceinline__ void ldsm4(uint32_t* r, uint32_t addr) {
    asm volatile("ldmatrix.sync.aligned.m8n8.x4.shared.b16 {%0,%1,%2,%3}, [%4];"
                 : "=r"(r[0]), "=r"(r[1]), "=r"(r[2]), "=r"(r[3]) : "r"(addr));
}
__device__ __forceinline__ void cpa16(uint32_t saddr, const void* g) {
    asm volatile("cp.async.cg.shared.global [%0], [%1], 16;" :: "r"(saddr), "l"(g) : "memory");
}
#define CP_COMMIT() asm volatile("cp.async.commit_group;" ::: "memory")
#define CP_WAIT0()  asm volatile("cp.async.wait_group 0;" ::: "memory")

__device__ __forceinline__ uint32_t a_addr(uint32_t base, int row0, int col,
                                           int strideB, int lane) {
    int gsel = lane >> 3, ln = lane & 7;
    return base + (uint32_t)((row0 + ((gsel & 1) << 3) + ln) * strideB
                             + ((col + ((gsel >> 1) << 3)) << 1));
}
__device__ __forceinline__ uint32_t b_addr(uint32_t base, int row0, int col,
                                           int strideB, int lane) {
    int gsel = lane >> 3, ln = lane & 7;
    return base + (uint32_t)((row0 + ((gsel >> 1) << 3) + ln) * strideB
                             + ((col + ((gsel & 1) << 3)) << 1));
}

// SMEM layout (byte strides: stride % 128 == 16 -> conflict-free LDSM phases)
#define QSTRB 528
#define STSTRB 144
#define PSTRB 272
#define SCSTRB 272
#define O_QHI 0
#define O_QLO 33792
#define O_PHI 67584
#define O_PLO 84992
#define O_STAGE 102400
#define BUFB 36864
#define LOOFF 18432
#define O_EPI (O_STAGE + BUFB)
#define EPSTR 65
#define O_LP 176128
#define SMEM_TOTAL (O_LP + 64 * 4 * 4)   // 177152

__device__ __forceinline__ void stage_st_chunk(uint32_t dhi,
        const __nv_bfloat16* sth, const __nv_bfloat16* stl,
        int s0, int cc, int tid) {
    for (int i = tid; i < 128 * 8; i += 256) {
        int r = i >> 3, c16 = i & 7;
        uint32_t so = (uint32_t)(r * STSTRB + c16 * 16);
        size_t go = (size_t)(s0 + r) * C_DIM + cc * 64 + c16 * 8;
        cpa16(dhi + so, sth + go);
        cpa16(dhi + LOOFF + so, stl + go);
    }
}
__device__ __forceinline__ void stage_sc_chunk(uint32_t dhi,
        const __nv_bfloat16* sh, const __nv_bfloat16* sl,
        int s0, int nc, int tid) {
    for (int i = tid; i < 64 * 16; i += 256) {
        int r = i >> 4, c16 = i & 15;
        uint32_t so = (uint32_t)(r * SCSTRB + c16 * 16);
        size_t go = (size_t)(nc * 64 + r) * L_S + s0 + c16 * 8;
        cpa16(dhi + so, sh + go);
        cpa16(dhi + LOOFF + so, sl + go);
    }
}

// ---------------- fused HMMA attention ----------------
// grid 128 = g(2) * b(4) * ltile(16); block 256 (8 warps, wr(2) x wc(4))
__global__ __launch_bounds__(256, 1)
void attn_mma_kernel(float* __restrict__ out_aligned) {
    extern __shared__ char sm[];
    const uint32_t smb = smem_u32(sm);
    const int tid = threadIdx.x;
    const int w = tid >> 5, lane = tid & 31;
    const int r = lane >> 2, q = lane & 3;
    const int wr = w >> 2, wc = w & 3;

    const int bid = blockIdx.x;
    const int lt = bid & 15, b = (bid >> 4) & 3, g = bid >> 6;
    const int l0 = lt << 6;

    float* Lp = (float*)(sm + O_LP);  // [64][4]
    float* epi = (float*)(sm + O_EPI);

    // prologue: resident Q tile + first S^T chunk (one cp.async group)
    {
        const __nv_bfloat16* qh = g_qthi + ((size_t)b * L_Q + l0) * C_DIM;
        const __nv_bfloat16* ql = g_qtlo + ((size_t)b * L_Q + l0) * C_DIM;
        for (int i = tid; i < 64 * 32; i += 256) {
            int row = i >> 5, c16 = i & 31;
            uint32_t so = (uint32_t)(row * QSTRB + c16 * 16);
            const size_t go = (size_t)row * C_DIM + c16 * 8;
            cpa16(smb + O_QHI + so, qh + go);
            cpa16(smb + O_QLO + so, ql + go);
        }
        const int n0 = g * K_SHOT;
        stage_st_chunk(smb + O_STAGE, g_sthi + (size_t)n0 * L_S * C_DIM,
                       g_stlo + (size_t)n0 * L_S * C_DIM, 0, 0, tid);
        CP_COMMIT();
    }

    float* outp = out_aligned + ((size_t)((g * B_DIM + b) * C_DIM) << 10);

    // K-shot average accumulator (registers)
    float avg[4][2][2][4];
#pragma unroll
    for (int a = 0; a < 4; a++)
#pragma unroll
        for (int m = 0; m < 2; m++)
#pragma unroll
            for (int j = 0; j < 2; j++)
#pragma unroll
                for (int v = 0; v < 4; v++) avg[a][m][j][v] = 0.f;

    for (int k = 0; k < K_SHOT; k++) {
        const int n = g * K_SHOT + k;
        const __nv_bfloat16* sth = g_sthi + (size_t)n * L_S * C_DIM;
        const __nv_bfloat16* stl = g_stlo + (size_t)n * L_S * C_DIM;
        const __nv_bfloat16* sh  = g_shi + (size_t)n * C_DIM * L_S;
        const __nv_bfloat16* sl  = g_slo + (size_t)n * C_DIM * L_S;

        Lp[tid] = 0.f;

        float acc2[4][2][2][4];
#pragma unroll
        for (int a = 0; a < 4; a++)
#pragma unroll
            for (int m = 0; m < 2; m++)
#pragma unroll
                for (int j = 0; j < 2; j++)
#pragma unroll
                    for (int v = 0; v < 4; v++) acc2[a][m][j][v] = 0.f;

        for (int st = 0; st < 8; st++) {
            const int s0 = st << 7;

            // ======== GEMM1: single-sync pipelined chunks ========
            float acc1[2][4][4];
#pragma unroll
            for (int m = 0; m < 2; m++)
#pragma unroll
                for (int j = 0; j < 4; j++)
#pragma unroll
                    for (int v = 0; v < 4; v++) acc1[m][j][v] = 0.f;

            for (int cc = 0; cc < 4; cc++) {
                const uint32_t cur = smb + O_STAGE + (uint32_t)(cc & 1) * BUFB;
                CP_WAIT0();
                __syncthreads();  // chunk cc ready; chunk cc-1 readers retired
                if (cc < 3) {
                    stage_st_chunk(smb + O_STAGE + (uint32_t)((cc + 1) & 1) * BUFB,
                                   sth, stl, s0, cc + 1, tid);
                    CP_COMMIT();
                } else {
                    stage_sc_chunk(smb + O_STAGE, sh, sl, s0, 0, tid);
                    CP_COMMIT();
                }

#pragma unroll
                for (int ks = 0; ks < 4; ks++) {
                    const int colq = cc * 64 + ks * 16;
                    uint32_t ah[2][4], al_[2][4];
                    ldsm4(ah[0],  a_addr(smb + O_QHI, wr * 32,      colq, QSTRB, lane));
                    ldsm4(ah[1],  a_addr(smb + O_QHI, wr * 32 + 16, colq, QSTRB, lane));
                    ldsm4(al_[0], a_addr(smb + O_QLO, wr * 32,      colq, QSTRB, lane));
                    ldsm4(al_[1], a_addr(smb + O_QLO, wr * 32 + 16, colq, QSTRB, lane));
                    uint32_t bh[4][2], bl[4][2];
                    {
                        uint32_t t[4];
                        ldsm4(t, b_addr(cur, wc * 32,      ks * 16, STSTRB, lane));
                        bh[0][0] = t[0]; bh[0][1] = t[1]; bh[1][0] = t[2]; bh[1][1] = t[3];
                        ldsm4(t, b_addr(cur, wc * 32 + 16, ks * 16, STSTRB, lane));
                        bh[2][0] = t[0]; bh[2][1] = t[1]; bh[3][0] = t[2]; bh[3][1] = t[3];
                        ldsm4(t, b_addr(cur + LOOFF, wc * 32,      ks * 16, STSTRB, lane));
                        bl[0][0] = t[0]; bl[0][1] = t[1]; bl[1][0] = t[2]; bl[1][1] = t[3];
                        ldsm4(t, b_addr(cur + LOOFF, wc * 32 + 16, ks * 16, STSTRB, lane));
                        bl[2][0] = t[0]; bl[2][1] = t[1]; bl[3][0] = t[2]; bl[3][1] = t[3];
                    }
#pragma unroll
                    for (int m = 0; m < 2; m++)
#pragma unroll
                        for (int j = 0; j < 4; j++) {
                            mma16816(acc1[m][j], ah[m], bh[j]);
                            mma16816(acc1[m][j], ah[m], bl[j]);
                            mma16816(acc1[m][j], al_[m], bh[j]);
                        }
                }
            }

            // ======== softmax: P = exp(sim - SHIFT), hi/lo -> SMEM ========
            // (overlaps with in-flight sc0 staging; published by GEMM2 nc0 sync)
            {
                float rowsum[2][2] = {{0.f, 0.f}, {0.f, 0.f}};
                float pv[2][4][4];
#pragma unroll
                for (int m = 0; m < 2; m++)
#pragma unroll
                    for (int j = 0; j < 4; j++) {
#pragma unroll
                        for (int v = 0; v < 4; v++)
                            pv[m][j][v] = __expf(acc1[m][j][v] - SHIFT_CONST);
                        rowsum[m][0] += pv[m][j][0] + pv[m][j][1];
                        rowsum[m][1] += pv[m][j][2] + pv[m][j][3];
                    }
#pragma unroll
                for (int m = 0; m < 2; m++)
#pragma unroll
                    for (int h = 0; h < 2; h++) {
                        rowsum[m][h] += __shfl_xor_sync(0xffffffffu, rowsum[m][h], 1);
                        rowsum[m][h] += __shfl_xor_sync(0xffffffffu, rowsum[m][h], 2);
                    }
#pragma unroll
                for (int m = 0; m < 2; m++)
#pragma unroll
                    for (int j = 0; j < 4; j++)
#pragma unroll
                        for (int h = 0; h < 2; h++) {
                            int prow = wr * 32 + m * 16 + r + h * 8;
                            int pcol = wc * 32 + j * 8 + q * 2;
                            float p0 = pv[m][j][h * 2 + 0];
                            float p1 = pv[m][j][h * 2 + 1];
                            __nv_bfloat162 th = __floats2bfloat162_rn(p0, p1);
                            float r0 = p0 - __low2float(th);
                            float r1 = p1 - __high2float(th);
                            __nv_bfloat162 tl = __floats2bfloat162_rn(r0, r1);
                            *(uint32_t*)(sm + O_PHI + prow * PSTRB + pcol * 2) =
                                *reinterpret_cast<uint32_t*>(&th);
                            *(uint32_t*)(sm + O_PLO + prow * PSTRB + pcol * 2) =
                                *reinterpret_cast<uint32_t*>(&tl);
                        }
                if (q == 0) {
#pragma unroll
                    for (int m = 0; m < 2; m++)
#pragma unroll
                        for (int h = 0; h < 2; h++) {
                            int prow = wr * 32 + m * 16 + r + h * 8;
                            Lp[prow * 4 + wc] += rowsum[m][h];
                        }
                }
            }

            // ======== GEMM2: single-sync pipelined chunks ========
            for (int nc = 0; nc < 4; nc++) {
                const uint32_t cur = smb + O_STAGE + (uint32_t)(nc & 1) * BUFB;
                CP_WAIT0();
                __syncthreads();  // chunk ready; P visible (nc==0); prev readers retired
                if (nc < 3) {
                    stage_sc_chunk(smb + O_STAGE + (uint32_t)((nc + 1) & 1) * BUFB,
                                   sh, sl, s0, nc + 1, tid);
                    CP_COMMIT();
                } else {
                    int k2 = k, st2 = st + 1;
                    if (st2 == 8) { st2 = 0; k2 = k + 1; }
                    if (k2 < K_SHOT) {
                        const int n2 = g * K_SHOT + k2;
                        stage_st_chunk(smb + O_STAGE,
                                       g_sthi + (size_t)n2 * L_S * C_DIM,
                                       g_stlo + (size_t)n2 * L_S * C_DIM,
                                       st2 << 7, 0, tid);
                        CP_COMMIT();
                    }
                }

#pragma unroll
                for (int ks = 0; ks < 8; ks++) {
                    uint32_t ah[2][4], al_[2][4];
                    ldsm4(ah[0],  a_addr(smb + O_PHI, wr * 32,      ks * 16, PSTRB, lane));
                    ldsm4(ah[1],  a_addr(smb + O_PHI, wr * 32 + 16, ks * 16, PSTRB, lane));
                    ldsm4(al_[0], a_addr(smb + O_PLO, wr * 32,      ks * 16, PSTRB, lane));
                    ldsm4(al_[1], a_addr(smb + O_PLO, wr * 32 + 16, ks * 16, PSTRB, lane));
                    uint32_t bh[2][2], bl[2][2];
                    {
                        uint32_t t[4];
                        ldsm4(t, b_addr(cur, wc * 16, ks * 16, SCSTRB, lane));
                        bh[0][0] = t[0]; bh[0][1] = t[1]; bh[1][0] = t[2]; bh[1][1] = t[3];
                        ldsm4(t, b_addr(cur + LOOFF, wc * 16, ks * 16, SCSTRB, lane));
                        bl[0][0] = t[0]; bl[0][1] = t[1]; bl[1][0] = t[2]; bl[1][1] = t[3];
                    }
#pragma unroll
                    for (int m = 0; m < 2; m++)
#pragma unroll
                        for (int j = 0; j < 2; j++) {
                            mma16816(acc2[nc][m][j], ah[m], bh[j]);
                            mma16816(acc2[nc][m][j], ah[m], bl[j]);
                            mma16816(acc2[nc][m][j], al_[m], bh[j]);
                        }
                }
            }
        }  // s-tiles

        // ======== shot end: avg += acc2 * (0.2/L[row]) (registers only) ========
        {
            float scl[2][2];
#pragma unroll
            for (int m = 0; m < 2; m++)
#pragma unroll
                for (int h = 0; h < 2; h++) {
                    int row = wr * 32 + m * 16 + r + h * 8;
                    float L = Lp[row * 4] + Lp[row * 4 + 1] + Lp[row * 4 + 2] + Lp[row * 4 + 3];
                    scl[m][h] = 0.2f / L;
                }
#pragma unroll
            for (int nc = 0; nc < 4; nc++)
#pragma unroll
                for (int m = 0; m < 2; m++)
#pragma unroll
                    for (int j = 0; j < 2; j++)
#pragma unroll
                        for (int v = 0; v < 4; v++)
                            avg[nc][m][j][v] += acc2[nc][m][j][v] * scl[m][v >> 1];
        }
        __syncthreads();  // Lp reads done before next shot's reset
    }  // shots

    // ======== final epilogue: coalesced pure stores ========
    for (int nc = 0; nc < 4; nc++) {
        __syncthreads();
#pragma unroll
        for (int m = 0; m < 2; m++)
#pragma unroll
            for (int j = 0; j < 2; j++)
#pragma unroll
                for (int v = 0; v < 4; v++) {
                    int row = wr * 32 + m * 16 + r + (v >> 1) * 8;
                    int col = wc * 16 + j * 8 + q * 2 + (v & 1);
                    epi[row * EPSTR + col] = avg[nc][m][j][v];
                }
        __syncthreads();
#pragma unroll
        for (int cidx = 0; cidx < 8; cidx++) {
            int colL = w * 8 + cidx;
            size_t oa = ((size_t)(nc * 64 + colL) << 10) + l0 + lane * 2;
            float v0 = epi[(lane * 2) * EPSTR + colL];
            float v1 = epi[(lane * 2 + 1) * EPSTR + colL];
            *reinterpret_cast<float2*>(outp + oa) = make_float2(v0, v1);
        }
    }
}

extern "C" void kernel_launch(void* const* d_in, const int* in_sizes, int n_in,
                              void* d_out, int out_size) {
    const float* q = (const float*)d_in[0];
    const float* s = (const float*)d_in[1];
    float* out = (float*)d_out;
    float* out_aligned = out + (size_t)QOUT_ELEMS;

    cudaFuncSetAttribute(attn_mma_kernel, cudaFuncAttributeMaxDynamicSharedMemorySize, SMEM_TOTAL);

    partial_sum_kernel<<<512, 256>>>(q, Q_ELEMS, 0);
    partial_sum_kernel<<<512, 256>>>(s, S_ELEMS, 1);
    final_mean_kernel<<<1, 512>>>();

    dim3 tb(32, 8);
    prep_qt_kernel<<<dim3(L_Q / 32, C_DIM / 32, B_DIM), tb>>>(q);
    prep_st_kernel<<<dim3(L_S / 32, C_DIM / 32, N_DIM), tb>>>(s);

    qout_kernel<<<(QOUT_ELEMS + 255) / 256, 256>>>(q, out);
    attn_mma_kernel<<<G_DIM * B_DIM * 16, 256, SMEM_TOTAL>>>(out_aligned);
}